// round 7
// baseline (speedup 1.0000x reference)
#include <cuda_runtime.h>
#include <cuda_fp16.h>

#define BB 8
#define NN 4096
#define EE 8190
#define VV 256
#define HH 128
#define TS 131072          // hash table slots (2^17)
#define TSM (TS - 1)
#define CAP 32             // adjacency capacity per node
#define GG 400             // persistent blocks (3/SM capacity = 444 >= 400 -> all resident)
#define TT 512             // threads per block
#define NNODE (BB * NN)    // 32768
#define SMEM_BYTES (VV * HH * 2)   // 64KB fp16 emb1

// -------- scratch (device globals; zero-initialized, kept clean by each launch) ------
__device__ unsigned int g_tab[TS];             // dedup hash table (key+1, 0=empty)
__device__ int          g_rowcnt[NNODE];       // out-degree
__device__ int          g_incnt[NNODE];        // in-degree
__device__ int          g_adjo[NNODE * CAP];   // out entries: j | (type_j<<12)
__device__ int          g_adji[NNODE * CAP];   // in entries: i
__device__ __half       g_emb1h[VV * HH];      // emb @ w1^T (fp16)
__device__ float        g_pooled[BB * HH];
__device__ unsigned int g_bar_cnt;
__device__ unsigned int g_bar_gen;

__device__ __forceinline__ void gridbar() {
    __syncthreads();
    if (threadIdx.x == 0) {
        __threadfence();
        unsigned gen = *((volatile unsigned*)&g_bar_gen);
        if (atomicAdd(&g_bar_cnt, 1u) == gridDim.x - 1) {
            *((volatile unsigned*)&g_bar_cnt) = 0u;
            __threadfence();
            *((volatile unsigned*)&g_bar_gen) = gen + 1u;
        } else {
            while (*((volatile unsigned*)&g_bar_gen) == gen) { }
            __threadfence();
        }
    }
    __syncthreads();
}

extern __shared__ __half s_e1[];   // [VV*HH] fp16 emb1

__global__ void __launch_bounds__(TT, 3)
gnn_all(const int* __restrict__ type_ids, const int* __restrict__ edges,
        const float* __restrict__ emb, const float* __restrict__ w1,
        const float* __restrict__ b1, const float* __restrict__ w2,
        const float* __restrict__ b2, float* __restrict__ out) {
    const int tid  = threadIdx.x;
    const int gtid = blockIdx.x * TT + tid;
    const int lane = tid & 31;
    const int gw   = gtid >> 5;
    const int nw   = (GG * TT) >> 5;          // 6400 warps

    // ---- P1a: edge dedup (set semantics) + adjacency build at insert time ----
    if (gtid < BB * EE) {
        int b = gtid / EE;
        int2 e = reinterpret_cast<const int2*>(edges)[gtid];
        unsigned key1 = (((unsigned)b << 24) | ((unsigned)e.x << 12) | (unsigned)e.y) + 1u;
        unsigned s = ((key1 * 0x9E3779B1u) >> 15) & TSM;
        while (true) {
            unsigned prev = atomicCAS(&g_tab[s], 0u, key1);
            if (prev == 0u) {
                int ni = b * NN + e.x;
                int nj = b * NN + e.y;
                int oc = atomicAdd(&g_rowcnt[ni], 1);
                if (oc < CAP) g_adjo[ni * CAP + oc] = e.y | (type_ids[nj] << 12);
                int ic = atomicAdd(&g_incnt[nj], 1);
                if (ic < CAP) g_adji[nj * CAP + ic] = e.x;
                break;
            }
            if (prev == key1) break;
            s = (s + 1) & TSM;
        }
    }
    // ---- P1b: emb1 = emb @ w1^T ; warp-task = (v, block of 8 cols) ----
    if (gw < VV * (HH / 8)) {                  // 4096 tasks, one per warp
        int v    = gw >> 4;
        int c0   = (gw & 15) * 8;
        const float* er = emb + v * HH;
        float ev[4];
        #pragma unroll
        for (int q = 0; q < 4; q++) ev[q] = er[lane + 32 * q];
        float p[8];
        #pragma unroll
        for (int cc = 0; cc < 8; cc++) {       // batched partials: 32 indep LDGs
            const float* wr = w1 + (c0 + cc) * HH;
            float a = 0.f;
            #pragma unroll
            for (int q = 0; q < 4; q++) a = fmaf(ev[q], wr[lane + 32 * q], a);
            p[cc] = a;
        }
        __half res = __float2half(0.f);
        #pragma unroll
        for (int cc = 0; cc < 8; cc++) {
            float a = p[cc];
            #pragma unroll
            for (int off = 16; off; off >>= 1) a += __shfl_xor_sync(0xffffffffu, a, off);
            if (lane == cc) res = __float2half(a);
        }
        if (lane < 8) g_emb1h[v * HH + c0 + lane] = res;
    }
    gridbar();

    // ---- P2: stage emb1h to smem; per node h = relu(di*(di*e1+S)+b1); pool ----
    for (int i = tid; i < (VV * HH * 2) / 16; i += TT)
        reinterpret_cast<uint4*>(s_e1)[i] = reinterpret_cast<const uint4*>(g_emb1h)[i];
    __syncthreads();
    {
        float bias[4], acc[BB > 1 ? 4 : 4];
        float4 b4 = reinterpret_cast<const float4*>(b1)[lane];   // cols lane*4..+3
        bias[0] = b4.x; bias[1] = b4.y; bias[2] = b4.z; bias[3] = b4.w;
        int curb = -1;
        float pac[4] = {0.f, 0.f, 0.f, 0.f};
        for (int ni = gw; ni < NNODE; ni += nw) {
            int b  = ni >> 12;
            int bN = b << 12;
            if (b != curb) {                   // flush pooled acc on batch switch
                if (curb >= 0) {
                    #pragma unroll
                    for (int q = 0; q < 4; q++)
                        atomicAdd(&g_pooled[curb * HH + lane * 4 + q], pac[q]);
                    #pragma unroll
                    for (int q = 0; q < 4; q++) pac[q] = 0.f;
                }
                curb = b;
            }
            int oc = g_rowcnt[ni];
            int ic = g_incnt[ni];
            int ty = type_ids[ni];
            int4 oe = *reinterpret_cast<const int4*>(&g_adjo[ni * CAP]);
            int4 ie = *reinterpret_cast<const int4*>(&g_adji[ni * CAP]);
            float di = rsqrtf(1.0f + (float)oc);
            // out-neighbor dis (independent uniform loads, MLP 4)
            int vj[4] = {oe.x, oe.y, oe.z, oe.w};
            float dj[4];
            #pragma unroll
            for (int q = 0; q < 4; q++)
                dj[q] = (oc > q) ? rsqrtf(1.0f + (float)g_rowcnt[bN + (vj[q] & 4095)]) : 0.f;
            // gather rows from smem (half2 pairs)
            float sacc[4];
            {
                uint2 r = reinterpret_cast<const uint2*>(s_e1 + ty * HH)[lane];
                float2 lo = __half22float2(*reinterpret_cast<__half2*>(&r.x));
                float2 hi = __half22float2(*reinterpret_cast<__half2*>(&r.y));
                sacc[0] = di * lo.x; sacc[1] = di * lo.y;
                sacc[2] = di * hi.x; sacc[3] = di * hi.y;
            }
            #pragma unroll
            for (int q = 0; q < 4; q++) {
                if (oc > q) {
                    int t = vj[q] >> 12;
                    uint2 r = reinterpret_cast<const uint2*>(s_e1 + t * HH)[lane];
                    float2 lo = __half22float2(*reinterpret_cast<__half2*>(&r.x));
                    float2 hi = __half22float2(*reinterpret_cast<__half2*>(&r.y));
                    sacc[0] = fmaf(dj[q], lo.x, sacc[0]);
                    sacc[1] = fmaf(dj[q], lo.y, sacc[1]);
                    sacc[2] = fmaf(dj[q], hi.x, sacc[2]);
                    sacc[3] = fmaf(dj[q], hi.y, sacc[3]);
                }
            }
            if (oc > 4) {                      // rare tail
                int dmax = min(oc, CAP);
                for (int d = 4; d < dmax; d++) {
                    int v = g_adjo[ni * CAP + d];
                    float w = rsqrtf(1.0f + (float)g_rowcnt[bN + (v & 4095)]);
                    int t = v >> 12;
                    uint2 r = reinterpret_cast<const uint2*>(s_e1 + t * HH)[lane];
                    float2 lo = __half22float2(*reinterpret_cast<__half2*>(&r.x));
                    float2 hi = __half22float2(*reinterpret_cast<__half2*>(&r.y));
                    sacc[0] = fmaf(w, lo.x, sacc[0]);
                    sacc[1] = fmaf(w, lo.y, sacc[1]);
                    sacc[2] = fmaf(w, hi.x, sacc[2]);
                    sacc[3] = fmaf(w, hi.y, sacc[3]);
                }
            }
            // incoming dis sum (column weight)
            float ins = 0.f;
            int wi[4] = {ie.x, ie.y, ie.z, ie.w};
            #pragma unroll
            for (int q = 0; q < 4; q++)
                if (ic > q) ins += rsqrtf(1.0f + (float)g_rowcnt[bN + (wi[q] & 4095)]);
            if (ic > 4) {
                int dmax = min(ic, CAP);
                for (int d = 4; d < dmax; d++)
                    ins += rsqrtf(1.0f + (float)g_rowcnt[bN + (g_adji[ni * CAP + d] & 4095)]);
            }
            float cc = di * (di + ins);
            #pragma unroll
            for (int q = 0; q < 4; q++) {
                float hv = fmaxf(fmaf(di, sacc[q], bias[q]), 0.f);
                pac[q] = fmaf(cc, hv, pac[q]);
            }
        }
        if (curb >= 0) {
            #pragma unroll
            for (int q = 0; q < 4; q++)
                atomicAdd(&g_pooled[curb * HH + lane * 4 + q], pac[q]);
        }
    }
    gridbar();

    // ---- P3: blocks 0..7: GEMV + normalize (+ zero pooled); blocks 8+: clear scratch --
    if (blockIdx.x < BB) {
        const int b = blockIdx.x;
        __shared__ float xs[HH];
        __shared__ float zsh[HH];
        __shared__ float nsum;
        if (tid < HH) {
            xs[tid] = g_pooled[b * HH + tid] * (1.0f / NN);
            g_pooled[b * HH + tid] = 0.f;          // deferred clean for next launch
        }
        if (tid == 0) nsum = 0.f;
        __syncthreads();
        const int w = tid >> 5;                    // 16 warps -> 8 rows each
        float sqp = 0.f;
        for (int r = w * 8; r < w * 8 + 8; r++) {
            const float* wr = w2 + r * HH;
            float p = 0.f;
            #pragma unroll
            for (int q = 0; q < 4; q++) { int k = lane + q * 32; p = fmaf(wr[k], xs[k], p); }
            #pragma unroll
            for (int off = 16; off; off >>= 1) p += __shfl_xor_sync(0xffffffffu, p, off);
            if (lane == 0) {
                float z = p + b2[r];
                zsh[r] = z;
                sqp = fmaf(z, z, sqp);
            }
        }
        if (lane == 0) atomicAdd(&nsum, sqp);
        __syncthreads();
        if (tid < HH) {
            float nrm = fmaxf(sqrtf(nsum), 1e-12f);
            out[b * HH + tid] = zsh[tid] / nrm;
        }
    } else {
        // clear table + degree counters for the next launch (adjacency is degree-gated)
        int cid = (blockIdx.x - BB) * TT + tid;
        int csz = (GG - BB) * TT;
        uint4 z4 = make_uint4(0u, 0u, 0u, 0u);
        for (int i = cid; i < TS / 4; i += csz)
            reinterpret_cast<uint4*>(g_tab)[i] = z4;
        for (int i = cid; i < NNODE / 4; i += csz) {
            reinterpret_cast<uint4*>(g_rowcnt)[i] = z4;
            reinterpret_cast<uint4*>(g_incnt)[i] = z4;
        }
    }
}

extern "C" void kernel_launch(void* const* d_in, const int* in_sizes, int n_in,
                              void* d_out, int out_size) {
    const int*   type_ids = (const int*)d_in[0];
    const int*   edges    = (const int*)d_in[1];
    const float* emb      = (const float*)d_in[2];
    const float* w1       = (const float*)d_in[3];
    const float* b1       = (const float*)d_in[4];
    const float* w2       = (const float*)d_in[5];
    const float* b2       = (const float*)d_in[6];
    float* out = (float*)d_out;

    static int smem_set = 0;
    if (!smem_set) {
        cudaFuncSetAttribute(gnn_all, cudaFuncAttributeMaxDynamicSharedMemorySize, SMEM_BYTES);
        smem_set = 1;
    }
    gnn_all<<<GG, TT, SMEM_BYTES>>>(type_ids, edges, emb, w1, b1, w2, b2, out);
}

// round 8
// speedup vs baseline: 6.0264x; 6.0264x over previous
#include <cuda_runtime.h>
#include <cuda_fp16.h>

#define BB 8
#define NN 4096
#define EE 8190
#define VV 256
#define HH 128
#define TS 131072          // hash table slots (2^17)
#define TSM (TS - 1)
#define CAP 32             // adjacency capacity per node
#define NNODE (BB * NN)    // 32768

// -------- scratch (device globals; zero-initialized; k_final re-cleans per launch) ----
__device__ unsigned int g_tab[TS];             // dedup hash table (key+1, 0=empty)
__device__ int          g_rowcnt[NNODE];       // unique out-degree
__device__ int          g_incnt[NNODE];        // unique in-degree
__device__ int          g_adjo[NNODE * CAP];   // out entries: j | (type_j<<12)
__device__ int          g_adji[NNODE * CAP];   // in entries: i
__device__ __half       g_emb1h[VV * HH];      // emb @ w1^T (fp16, 64KB -> L2-hot)
__device__ float        g_pooled[BB * HH];

// ==== K1: blocks 0..255 dedup+adjacency; blocks 256..383 emb1 = emb @ w1^T (fp16) ====
__global__ void __launch_bounds__(256)
k_build(const int* __restrict__ type_ids, const int* __restrict__ edges,
        const float* __restrict__ emb, const float* __restrict__ w1) {
    const int tid = threadIdx.x;
    const int lane = tid & 31;
    if (blockIdx.x < 256) {
        int t = blockIdx.x * 256 + tid;
        if (t >= BB * EE) return;
        int b = t / EE;
        int2 e = reinterpret_cast<const int2*>(edges)[t];
        unsigned key1 = (((unsigned)b << 24) | ((unsigned)e.x << 12) | (unsigned)e.y) + 1u;
        unsigned s = ((key1 * 0x9E3779B1u) >> 15) & TSM;
        while (true) {
            unsigned prev = atomicCAS(&g_tab[s], 0u, key1);
            if (prev == 0u) {                       // first inserter wins (set semantics)
                int ni = b * NN + e.x;
                int nj = b * NN + e.y;
                int oc = atomicAdd(&g_rowcnt[ni], 1);
                if (oc < CAP) g_adjo[ni * CAP + oc] = e.y | (type_ids[nj] << 12);
                int ic = atomicAdd(&g_incnt[nj], 1);
                if (ic < CAP) g_adji[nj * CAP + ic] = e.x;
                break;
            }
            if (prev == key1) break;                // duplicate: drop
            s = (s + 1) & TSM;
        }
    } else {
        // emb1: warp-task = (v, 8 output cols); 1024 warps x 4 tasks = 4096 tasks
        int wid = (blockIdx.x - 256) * 8 + (tid >> 5);
        #pragma unroll
        for (int q4 = 0; q4 < 4; q4++) {
            int task = wid + q4 * 1024;
            int v  = task >> 4;
            int c0 = (task & 15) * 8;
            const float* er = emb + v * HH;
            float ev[4];
            #pragma unroll
            for (int q = 0; q < 4; q++) ev[q] = er[lane + 32 * q];
            float p[8];
            #pragma unroll
            for (int cc = 0; cc < 8; cc++) {        // 32 independent coalesced LDGs
                const float* wr = w1 + (c0 + cc) * HH;
                float a = 0.f;
                #pragma unroll
                for (int q = 0; q < 4; q++) a = fmaf(ev[q], wr[lane + 32 * q], a);
                p[cc] = a;
            }
            __half res = __float2half(0.f);
            #pragma unroll
            for (int cc = 0; cc < 8; cc++) {
                float a = p[cc];
                #pragma unroll
                for (int off = 16; off; off >>= 1) a += __shfl_xor_sync(0xffffffffu, a, off);
                if (lane == cc) res = __float2half(a);
            }
            if (lane < 8) g_emb1h[v * HH + c0 + lane] = res;
        }
    }
}

// ==== K2: per node h = relu(di*(di*e1 + S) + b1); pooled += c_i*h  (L2-direct) ====
// 512 blocks x 256 thr = 4096 warps; warp handles 8 contiguous nodes; lane = 4 H-cols
__global__ void __launch_bounds__(256)
k_node(const int* __restrict__ type_ids, const float* __restrict__ b1) {
    const int lane = threadIdx.x & 31;
    const int gw   = blockIdx.x * 8 + (threadIdx.x >> 5);   // 0..4095
    const int base = gw * 8;                                // 8 nodes, same batch (8|4096)
    const int b    = base >> 12;
    const int bN   = b << 12;
    float4 b4 = reinterpret_cast<const float4*>(b1)[lane];
    float bias[4] = {b4.x, b4.y, b4.z, b4.w};
    float pac[4] = {0.f, 0.f, 0.f, 0.f};

    int oc[2], ic[2], ty[2]; int4 oe[2], ie[2];
    {   // prime node 0
        int ni = base;
        oc[0] = g_rowcnt[ni]; ic[0] = g_incnt[ni]; ty[0] = type_ids[ni];
        oe[0] = *reinterpret_cast<const int4*>(&g_adjo[ni * CAP]);
        ie[0] = *reinterpret_cast<const int4*>(&g_adji[ni * CAP]);
    }
    #pragma unroll
    for (int n = 0; n < 8; n++) {
        int cur = n & 1, nxt = cur ^ 1;
        if (n < 7) {                                 // prefetch next node meta (MLP 5)
            int ni = base + n + 1;
            oc[nxt] = g_rowcnt[ni]; ic[nxt] = g_incnt[ni]; ty[nxt] = type_ids[ni];
            oe[nxt] = *reinterpret_cast<const int4*>(&g_adjo[ni * CAP]);
            ie[nxt] = *reinterpret_cast<const int4*>(&g_adji[ni * CAP]);
        }
        int o_ = oc[cur], i_ = ic[cur];
        float di = rsqrtf(1.0f + (float)o_);
        int vj[4] = {oe[cur].x, oe[cur].y, oe[cur].z, oe[cur].w};
        float dj[4];
        #pragma unroll
        for (int q = 0; q < 4; q++)
            dj[q] = (o_ > q) ? rsqrtf(1.0f + (float)g_rowcnt[bN + (vj[q] & 4095)]) : 0.f;
        float sacc[4];
        {   // self row gather (identity term)
            uint2 r = reinterpret_cast<const uint2*>(g_emb1h + ty[cur] * HH)[lane];
            float2 lo = __half22float2(*reinterpret_cast<__half2*>(&r.x));
            float2 hi = __half22float2(*reinterpret_cast<__half2*>(&r.y));
            sacc[0] = di * lo.x; sacc[1] = di * lo.y;
            sacc[2] = di * hi.x; sacc[3] = di * hi.y;
        }
        #pragma unroll
        for (int q = 0; q < 4; q++) {
            if (o_ > q) {
                uint2 r = reinterpret_cast<const uint2*>(g_emb1h + (vj[q] >> 12) * HH)[lane];
                float2 lo = __half22float2(*reinterpret_cast<__half2*>(&r.x));
                float2 hi = __half22float2(*reinterpret_cast<__half2*>(&r.y));
                sacc[0] = fmaf(dj[q], lo.x, sacc[0]);
                sacc[1] = fmaf(dj[q], lo.y, sacc[1]);
                sacc[2] = fmaf(dj[q], hi.x, sacc[2]);
                sacc[3] = fmaf(dj[q], hi.y, sacc[3]);
            }
        }
        if (o_ > 4) {                                // rare tail
            int dmax = min(o_, CAP);
            for (int d = 4; d < dmax; d++) {
                int v = g_adjo[(base + n) * CAP + d];
                float w = rsqrtf(1.0f + (float)g_rowcnt[bN + (v & 4095)]);
                uint2 r = reinterpret_cast<const uint2*>(g_emb1h + (v >> 12) * HH)[lane];
                float2 lo = __half22float2(*reinterpret_cast<__half2*>(&r.x));
                float2 hi = __half22float2(*reinterpret_cast<__half2*>(&r.y));
                sacc[0] = fmaf(w, lo.x, sacc[0]);
                sacc[1] = fmaf(w, lo.y, sacc[1]);
                sacc[2] = fmaf(w, hi.x, sacc[2]);
                sacc[3] = fmaf(w, hi.y, sacc[3]);
            }
        }
        float ins = 0.f;
        int wi[4] = {ie[cur].x, ie[cur].y, ie[cur].z, ie[cur].w};
        #pragma unroll
        for (int q = 0; q < 4; q++)
            if (i_ > q) ins += rsqrtf(1.0f + (float)g_rowcnt[bN + (wi[q] & 4095)]);
        if (i_ > 4) {
            int dmax = min(i_, CAP);
            for (int d = 4; d < dmax; d++)
                ins += rsqrtf(1.0f + (float)g_rowcnt[bN + (g_adji[(base + n) * CAP + d] & 4095)]);
        }
        float cc = di * (di + ins);
        #pragma unroll
        for (int q = 0; q < 4; q++) {
            float hv = fmaxf(fmaf(di, sacc[q], bias[q]), 0.f);
            pac[q] = fmaf(cc, hv, pac[q]);
        }
    }
    #pragma unroll
    for (int q = 0; q < 4; q++)
        atomicAdd(&g_pooled[b * HH + lane * 4 + q], pac[q]);
}

// ==== K3: blocks 0..7 GEMV + L2-normalize (+ zero pooled); blocks 8..135 clear ====
__global__ void __launch_bounds__(256)
k_final(const float* __restrict__ w2, const float* __restrict__ b2,
        float* __restrict__ out) {
    const int tid = threadIdx.x;
    const int lane = tid & 31;
    if (blockIdx.x < BB) {
        const int b = blockIdx.x;
        __shared__ float xs[HH];
        __shared__ float zsh[HH];
        __shared__ float nsum;
        if (tid < HH) {
            xs[tid] = g_pooled[b * HH + tid] * (1.0f / NN);
            g_pooled[b * HH + tid] = 0.f;            // deferred clean for next launch
        }
        if (tid == 0) nsum = 0.f;
        __syncthreads();
        const int w = tid >> 5;                      // 8 warps -> 16 rows each
        float sqp = 0.f;
        for (int r = w * 16; r < w * 16 + 16; r++) {
            const float* wr = w2 + r * HH;
            float p = 0.f;
            #pragma unroll
            for (int q = 0; q < 4; q++) { int k = lane + q * 32; p = fmaf(wr[k], xs[k], p); }
            #pragma unroll
            for (int off = 16; off; off >>= 1) p += __shfl_xor_sync(0xffffffffu, p, off);
            if (lane == 0) {
                float z = p + b2[r];
                zsh[r] = z;
                sqp = fmaf(z, z, sqp);
            }
        }
        if (lane == 0) atomicAdd(&nsum, sqp);
        __syncthreads();
        if (tid < HH) {
            float nrm = fmaxf(sqrtf(nsum), 1e-12f);
            out[b * HH + tid] = zsh[tid] / nrm;
        }
    } else {
        // clear table + degree counters for next launch (adjacency is degree-gated)
        int cid = (blockIdx.x - BB) * 256 + tid;
        int csz = 128 * 256;
        uint4 z4 = make_uint4(0u, 0u, 0u, 0u);
        for (int i = cid; i < TS / 4; i += csz)
            reinterpret_cast<uint4*>(g_tab)[i] = z4;
        for (int i = cid; i < NNODE / 4; i += csz) {
            reinterpret_cast<uint4*>(g_rowcnt)[i] = z4;
            reinterpret_cast<uint4*>(g_incnt)[i] = z4;
        }
    }
}

extern "C" void kernel_launch(void* const* d_in, const int* in_sizes, int n_in,
                              void* d_out, int out_size) {
    const int*   type_ids = (const int*)d_in[0];
    const int*   edges    = (const int*)d_in[1];
    const float* emb      = (const float*)d_in[2];
    const float* w1       = (const float*)d_in[3];
    const float* b1       = (const float*)d_in[4];
    const float* w2       = (const float*)d_in[5];
    const float* b2       = (const float*)d_in[6];
    float* out = (float*)d_out;

    k_build<<<384, 256>>>(type_ids, edges, emb, w1);
    k_node<<<512, 256>>>(type_ids, b1);
    k_final<<<136, 256>>>(w2, b2, out);
}